// round 2
// baseline (speedup 1.0000x reference)
#include <cuda_runtime.h>
#include <cuda_bf16.h>
#include <cstdint>

// B=2, S=512, D=256, N=16, DC=4, DI=512, CHUNK=32, rows=1024
__device__ float g_xn   [1024*256];
__device__ float g_xp   [1024*512];
__device__ float g_sz   [1024*512];
__device__ float g_xact [1024*512];
__device__ float g_decay[1024*512];
__device__ float g_Bm   [1024*16];
__device__ float g_Cm   [1024*16];
__device__ float g_invdeg[1024];
__device__ float g_any  [1024];
__device__ float g_condT[512];
__device__ float g_P    [1024*512];

__global__ void __launch_bounds__(256) ln_kernel(const float* __restrict__ x,
                                                 const float* __restrict__ lw,
                                                 const float* __restrict__ lb) {
    __shared__ float red[256];
    int row = blockIdx.x, t = threadIdx.x;
    float v = x[row * 256 + t];
    red[t] = v; __syncthreads();
    for (int s = 128; s > 0; s >>= 1) { if (t < s) red[t] += red[t + s]; __syncthreads(); }
    float mu = red[0] * (1.0f / 256.0f); __syncthreads();
    float dv = v - mu;
    red[t] = dv * dv; __syncthreads();
    for (int s = 128; s > 0; s >>= 1) { if (t < s) red[t] += red[t + s]; __syncthreads(); }
    float var = red[0] * (1.0f / 256.0f);
    g_xn[row * 256 + t] = dv * rsqrtf(var + 1e-5f) * lw[t] + lb[t];
}

// xz = xn @ W_in^T (M=1024,N=1024,K=256); split xp / silu(z)
__global__ void __launch_bounds__(256) gemm_xz(const float* __restrict__ W_in) {
    __shared__ float As[16][64];
    __shared__ float Ws[16][64];
    int m0 = blockIdx.y * 64, n0 = blockIdx.x * 64;
    int tid = threadIdx.x, tr = tid >> 2, tc = tid & 3, ty = tid >> 4, tx = tid & 15;
    float acc[4][4] = {};
    for (int k0 = 0; k0 < 256; k0 += 16) {
        float4 av = *(const float4*)&g_xn[(m0 + tr) * 256 + k0 + (tc << 2)];
        As[(tc<<2)+0][tr]=av.x; As[(tc<<2)+1][tr]=av.y; As[(tc<<2)+2][tr]=av.z; As[(tc<<2)+3][tr]=av.w;
        float4 wv = *(const float4*)&W_in[(n0 + tr) * 256 + k0 + (tc << 2)];
        Ws[(tc<<2)+0][tr]=wv.x; Ws[(tc<<2)+1][tr]=wv.y; Ws[(tc<<2)+2][tr]=wv.z; Ws[(tc<<2)+3][tr]=wv.w;
        __syncthreads();
#pragma unroll
        for (int kk = 0; kk < 16; ++kk) {
            float4 a = *(const float4*)&As[kk][ty << 2];
            float4 w = *(const float4*)&Ws[kk][tx << 2];
            float aa[4]={a.x,a.y,a.z,a.w}, ww[4]={w.x,w.y,w.z,w.w};
#pragma unroll
            for (int i = 0; i < 4; ++i)
#pragma unroll
                for (int j = 0; j < 4; ++j) acc[i][j] += aa[i] * ww[j];
        }
        __syncthreads();
    }
#pragma unroll
    for (int i = 0; i < 4; ++i)
#pragma unroll
        for (int j = 0; j < 4; ++j) {
            int m = m0 + (ty << 2) + i, n = n0 + (tx << 2) + j;
            float v = acc[i][j];
            if (n < 512) g_xp[m * 512 + n] = v;
            else         g_sz[m * 512 + (n - 512)] = v / (1.0f + expf(-v));
        }
}

// xact = silu(conv(xp)+b): 4 shifted GEMM passes (M=1024,N=512,K=512)
__global__ void __launch_bounds__(256) gemm_conv(const float* __restrict__ conv_w,
                                                 const float* __restrict__ conv_b) {
    __shared__ float As[16][64];
    __shared__ float Ws[16][64];
    int m0 = blockIdx.y * 64, n0 = blockIdx.x * 64;
    int tid = threadIdx.x, tr = tid >> 2, tc = tid & 3, ty = tid >> 4, tx = tid & 15;
    float acc[4][4] = {};
    for (int kc = 0; kc < 4; ++kc) {
        int m = m0 + tr, t = m & 511, tsrc = t - 3 + kc;
        const float* arow = g_xp + (size_t)(m - 3 + kc) * 512;
        for (int k0 = 0; k0 < 512; k0 += 16) {
            float4 av = make_float4(0.f, 0.f, 0.f, 0.f);
            if (tsrc >= 0) av = *(const float4*)(arow + k0 + (tc << 2));
            As[(tc<<2)+0][tr]=av.x; As[(tc<<2)+1][tr]=av.y; As[(tc<<2)+2][tr]=av.z; As[(tc<<2)+3][tr]=av.w;
#pragma unroll
            for (int q = 0; q < 4; ++q)
                Ws[(tc << 2) + q][tr] = conv_w[(n0 + tr) * 2048 + (k0 + (tc << 2) + q) * 4 + kc];
            __syncthreads();
#pragma unroll
            for (int kk = 0; kk < 16; ++kk) {
                float4 a = *(const float4*)&As[kk][ty << 2];
                float4 w = *(const float4*)&Ws[kk][tx << 2];
                float aa[4]={a.x,a.y,a.z,a.w}, ww[4]={w.x,w.y,w.z,w.w};
#pragma unroll
                for (int i = 0; i < 4; ++i)
#pragma unroll
                    for (int j = 0; j < 4; ++j) acc[i][j] += aa[i] * ww[j];
            }
            __syncthreads();
        }
    }
#pragma unroll
    for (int i = 0; i < 4; ++i)
#pragma unroll
        for (int j = 0; j < 4; ++j) {
            int m = m0 + (ty << 2) + i, n = n0 + (tx << 2) + j;
            float v = acc[i][j] + conv_b[n];
            g_xact[m * 512 + n] = v / (1.0f + expf(-v));
        }
}

__global__ void __launch_bounds__(128) ssm_kernel(const float* __restrict__ W_xp,
                                                  const float* __restrict__ W_dt,
                                                  const float* __restrict__ b_dt) {
    __shared__ float xs[512];
    __shared__ float ssm_sh[33];
    int row = blockIdx.x, tid = threadIdx.x, lane = tid & 31, wid = tid >> 5;
    for (int i = tid; i < 512; i += 128) xs[i] = g_xact[row * 512 + i];
    __syncthreads();
    for (int o = wid; o < 33; o += 4) {
        float p = 0.f;
        for (int i = lane; i < 512; i += 32) p += xs[i] * W_xp[o * 512 + i];
        for (int k = 16; k > 0; k >>= 1) p += __shfl_xor_sync(0xffffffffu, p, k);
        if (lane == 0) ssm_sh[o] = p;
    }
    __syncthreads();
    if (tid < 16) {
        g_Bm[row * 16 + tid] = ssm_sh[1 + tid];
        g_Cm[row * 16 + tid] = ssm_sh[17 + tid];
    }
    float s0 = ssm_sh[0];
    for (int d = tid; d < 512; d += 128) {
        float v = s0 * W_dt[d] + b_dt[d];
        g_decay[row * 512 + d] = 1.0f / (1.0f + expf(v));  // exp(-softplus(v))
    }
}

__global__ void __launch_bounds__(256) deg_kernel(const float* __restrict__ adj) {
    __shared__ float rs[256];
    __shared__ int   ra[256];
    int row = blockIdx.x, b = row >> 9, t = row & 511;
    const float* a = adj + (size_t)(b * 512 + t) * 512;
    float s = 0.f; int any = 0;
    for (int i = threadIdx.x; i < t; i += 256) { float v = a[i]; s += v; any |= (v > 0.f); }
    rs[threadIdx.x] = s; ra[threadIdx.x] = any; __syncthreads();
    for (int k = 128; k > 0; k >>= 1) {
        if (threadIdx.x < k) { rs[threadIdx.x] += rs[threadIdx.x + k]; ra[threadIdx.x] |= ra[threadIdx.x + k]; }
        __syncthreads();
    }
    if (threadIdx.x == 0) {
        g_invdeg[row] = 1.0f / fmaxf(rs[0], 1.0f);
        g_any[row] = ra[0] ? 1.f : 0.f;
    }
}

__global__ void cond_kernel() {  // jnp.any reduces over ALL axes -> shared across batch
    int t = blockIdx.x * blockDim.x + threadIdx.x;
    if (t < 512) g_condT[t] = (t > 0 && (g_any[t] > 0.f || g_any[512 + t] > 0.f)) ? 1.f : 0.f;
}

// one block per (b,d); private 512x16 bf16 history
__global__ void __launch_bounds__(128) scan_kernel(const float* __restrict__ adj,
                                                   const float* __restrict__ Wr,
                                                   const float* __restrict__ br) {
    __shared__ __align__(16) __nv_bfloat16 hist[512][16];  // 16 KB
    __shared__ float adjT[32][33];
    __shared__ float adjC[32][33];
    __shared__ float Bs[32][16], Cs[32][16];
    __shared__ float dec_s[32], xa_s[32], ivd_s[32], cond_s[32];
    __shared__ float Wr_s[16][17];
    __shared__ float br_s[16];
    __shared__ float g_sh[16], h_sh[16];

    int tid = threadIdx.x, lane = tid & 31, wid = tid >> 5;
    int seq = blockIdx.x, b = seq >> 9, d = seq & 511;
    const float* adjb = adj + (size_t)b * 512 * 512;

    for (int i = tid; i < 256; i += 128) Wr_s[i >> 4][i & 15] = Wr[i];
    if (tid < 16) br_s[tid] = br[tid];

    float hreg = 0.0f;  // h[n=lane], lanes 0..15 of warp 0

    for (int c = 0; c < 16; ++c) {
        int c0 = c << 5;
        __syncthreads();
        if (tid < 32) {
            int row = b * 512 + c0 + tid;
            dec_s[tid]  = g_decay[row * 512 + d];
            xa_s[tid]   = g_xact [row * 512 + d];
            ivd_s[tid]  = g_invdeg[row];
            cond_s[tid] = g_condT[c0 + tid];
        }
        for (int i = tid; i < 512; i += 128) {
            int j = i >> 4, n = i & 15, row = b * 512 + c0 + j;
            Bs[j][n] = g_Bm[row * 16 + n];
            Cs[j][n] = g_Cm[row * 16 + n];
        }
        for (int i = tid; i < 1024; i += 128) {
            int tt = i >> 5, ss = i & 31;
            adjC[tt][ss] = adjb[(size_t)(c0 + tt) * 512 + c0 + ss];
        }

        // Gpre: contributions from all previous chunks (register-tiled matmul)
        float G0 = 0.f, G1 = 0.f, G2 = 0.f, G3 = 0.f;
        for (int st = 0; st < c; ++st) {
            __syncthreads();
            for (int i = tid; i < 1024; i += 128) {
                int tt = i >> 5, ss = i & 31;
                adjT[tt][ss] = adjb[(size_t)(c0 + tt) * 512 + (st << 5) + ss];
            }
            __syncthreads();
            int sbase = st << 5;
#pragma unroll 8
            for (int ss = 0; ss < 32; ++ss) {
                float a = adjT[lane][ss];
                unsigned long long hv = *(const unsigned long long*)&hist[sbase + ss][wid << 2];
                unsigned lo = (unsigned)hv, hi = (unsigned)(hv >> 32);
                G0 += a * __uint_as_float(lo << 16);
                G1 += a * __uint_as_float(lo & 0xFFFF0000u);
                G2 += a * __uint_as_float(hi << 16);
                G3 += a * __uint_as_float(hi & 0xFFFF0000u);
            }
        }
        __syncthreads();

        // sequential 32 steps
        for (int j = 0; j < 32; ++j) {
            if (lane == j) {
                g_sh[(wid<<2)+0]=G0; g_sh[(wid<<2)+1]=G1; g_sh[(wid<<2)+2]=G2; g_sh[(wid<<2)+3]=G3;
            }
            __syncthreads();
            if (tid < 16) {
                int n = tid;
                float gv = g_sh[n] * ivd_s[j];
                float accb = br_s[n];
#pragma unroll
                for (int m = 0; m < 16; ++m)
                    accb += Wr_s[n][m] * __shfl_sync(0x0000ffffu, gv, m, 16);
                float bo = 0.1f * accb / (1.0f + __expf(-accb));
                float h = hreg * dec_s[j] + xa_s[j] * Bs[j][n] + cond_s[j] * bo;
                hreg = h;
                h_sh[n] = h;
                hist[c0 + j][n] = __float2bfloat16(h);
                float y = h * Cs[j][n];
                y += __shfl_xor_sync(0x0000ffffu, y, 8, 16);
                y += __shfl_xor_sync(0x0000ffffu, y, 4, 16);
                y += __shfl_xor_sync(0x0000ffffu, y, 2, 16);
                y += __shfl_xor_sync(0x0000ffffu, y, 1, 16);
                if (n == 0) {
                    int row = b * 512 + c0 + j;
                    g_P[row * 512 + d] = y * g_sz[row * 512 + d];
                }
            }
            __syncthreads();
            if (lane > j) {
                float a = adjC[lane][j];
                G0 += a * h_sh[(wid<<2)+0];
                G1 += a * h_sh[(wid<<2)+1];
                G2 += a * h_sh[(wid<<2)+2];
                G3 += a * h_sh[(wid<<2)+3];
            }
        }
    }
}

// out = P @ W_out^T + x (M=1024,N=256,K=512)
__global__ void __launch_bounds__(256) gemm_out(const float* __restrict__ W_out,
                                                const float* __restrict__ x,
                                                float* __restrict__ out) {
    __shared__ float As[16][64];
    __shared__ float Ws[16][64];
    int m0 = blockIdx.y * 64, n0 = blockIdx.x * 64;
    int tid = threadIdx.x, tr = tid >> 2, tc = tid & 3, ty = tid >> 4, tx = tid & 15;
    float acc[4][4] = {};
    for (int k0 = 0; k0 < 512; k0 += 16) {
        float4 av = *(const float4*)&g_P[(m0 + tr) * 512 + k0 + (tc << 2)];
        As[(tc<<2)+0][tr]=av.x; As[(tc<<2)+1][tr]=av.y; As[(tc<<2)+2][tr]=av.z; As[(tc<<2)+3][tr]=av.w;
        float4 wv = *(const float4*)&W_out[(n0 + tr) * 512 + k0 + (tc << 2)];
        Ws[(tc<<2)+0][tr]=wv.x; Ws[(tc<<2)+1][tr]=wv.y; Ws[(tc<<2)+2][tr]=wv.z; Ws[(tc<<2)+3][tr]=wv.w;
        __syncthreads();
#pragma unroll
        for (int kk = 0; kk < 16; ++kk) {
            float4 a = *(const float4*)&As[kk][ty << 2];
            float4 w = *(const float4*)&Ws[kk][tx << 2];
            float aa[4]={a.x,a.y,a.z,a.w}, ww[4]={w.x,w.y,w.z,w.w};
#pragma unroll
            for (int i = 0; i < 4; ++i)
#pragma unroll
                for (int j = 0; j < 4; ++j) acc[i][j] += aa[i] * ww[j];
        }
        __syncthreads();
    }
#pragma unroll
    for (int i = 0; i < 4; ++i)
#pragma unroll
        for (int j = 0; j < 4; ++j) {
            int m = m0 + (ty << 2) + i, n = n0 + (tx << 2) + j;
            out[m * 256 + n] = acc[i][j] + x[m * 256 + n];
        }
}

extern "C" void kernel_launch(void* const* d_in, const int* in_sizes, int n_in,
                              void* d_out, int out_size) {
    const float* x      = (const float*)d_in[0];
    const float* adj    = (const float*)d_in[1];
    const float* ln_w   = (const float*)d_in[2];
    const float* ln_b   = (const float*)d_in[3];
    const float* W_in   = (const float*)d_in[4];
    const float* conv_w = (const float*)d_in[5];
    const float* conv_b = (const float*)d_in[6];
    const float* W_xp   = (const float*)d_in[7];
    const float* W_dt   = (const float*)d_in[8];
    const float* b_dt   = (const float*)d_in[9];
    const float* Wr     = (const float*)d_in[10];
    const float* br     = (const float*)d_in[11];
    const float* W_out  = (const float*)d_in[12];
    float* out = (float*)d_out;

    ln_kernel<<<1024, 256>>>(x, ln_w, ln_b);
    gemm_xz<<<dim3(16, 16), 256>>>(W_in);
    deg_kernel<<<1024, 256>>>(adj);
    cond_kernel<<<2, 256>>>();
    gemm_conv<<<dim3(8, 16), 256>>>(conv_w, conv_b);
    ssm_kernel<<<1024, 128>>>(W_xp, W_dt, b_dt);
    scan_kernel<<<1024, 128>>>(adj, Wr, br);
    gemm_out<<<dim3(4, 16), 256>>>(W_out, x, out);
}